// round 8
// baseline (speedup 1.0000x reference)
#include <cuda_runtime.h>

#define DD 96
#define HH 192
#define WW 192
#define W4N (WW/4)                // 48
#define NFULL (DD*HH*WW)          // 3538944
#define NQ    (NFULL/4)
#define NL1 (48*96*96)            // 442368
#define NL2 (24*48*48)            // 55296
#define NL3 (12*24*24)            // 6912

#define DT   0.01f
#define RE   0.001f
#define INVD (-1.0f/6.0f)         // 1/diag, diag = -6

// ---------------- scratch (device globals, float4-aligned) ----------------
__device__ float4 g_U4[NQ], g_V4[NQ], g_W4[NQ], g_INV4[NQ];
__device__ float4 g_BU4[NQ], g_BV4[NQ], g_BW4[NQ];
__device__ float4 g_R04[NQ], g_R0b4[NQ], g_P4[NQ];
__device__ float g_R1[NL1], g_R2[NL2], g_R3[NL3];
__device__ float g_W2[NL2], g_W1[NL1];

// ---------------- helpers ----------------
__device__ __forceinline__ float g(const float4 v, int k) {
    switch (k) { case 0: return v.x; case 1: return v.y; case 2: return v.z; default: return v.w; }
}
__device__ __forceinline__ void setk(float4& v, int k, float val) {
    switch (k) { case 0: v.x = val; break; case 1: v.y = val; break;
                 case 2: v.z = val; break; default: v.w = val; }
}

struct St { float4 c, ym, yp, zm, zp; float xm, xp; };

__device__ __forceinline__ St gather(const float* __restrict__ f, int z, int y, int x4) {
    St s;
    const float4* f4 = (const float4*)f;
    s.c  = f4[(z*HH + y)*W4N + x4];
    s.ym = (y > 0)    ? f4[(z*HH + y-1)*W4N + x4]   : make_float4(0,0,0,0);
    s.yp = (y < HH-1) ? f4[(z*HH + y+1)*W4N + x4]   : make_float4(0,0,0,0);
    s.zm = (z > 0)    ? f4[((z-1)*HH + y)*W4N + x4] : make_float4(0,0,0,0);
    s.zp = (z < DD-1) ? f4[((z+1)*HH + y)*W4N + x4] : make_float4(0,0,0,0);
    int base = (z*HH + y)*WW + 4*x4;
    s.xm = (x4 > 0)     ? f[base - 1] : 0.0f;
    s.xp = (x4 < W4N-1) ? f[base + 4] : 0.0f;
    return s;
}

__device__ __forceinline__ void damp(St& a, const St& s) {
    a.c.x*=s.c.x;   a.c.y*=s.c.y;   a.c.z*=s.c.z;   a.c.w*=s.c.w;
    a.ym.x*=s.ym.x; a.ym.y*=s.ym.y; a.ym.z*=s.ym.z; a.ym.w*=s.ym.w;
    a.yp.x*=s.yp.x; a.yp.y*=s.yp.y; a.yp.z*=s.yp.z; a.yp.w*=s.yp.w;
    a.zm.x*=s.zm.x; a.zm.y*=s.zm.y; a.zm.z*=s.zm.z; a.zm.w*=s.zm.w;
    a.zp.x*=s.zp.x; a.zp.y*=s.zp.y; a.zp.z*=s.zp.z; a.zp.w*=s.zp.w;
    a.xm*=s.xm;     a.xp*=s.xp;
}

#define NBRS(sf, k, fc, fxm, fxp, fym, fyp, fzm, fzp)                       \
    float fc  = g((sf).c, k);                                               \
    float fxm = (k)     ? g((sf).c, (k)-1) : (sf).xm;                       \
    float fxp = ((k)<3) ? g((sf).c, (k)+1) : (sf).xp;                       \
    float fym = g((sf).ym, k), fyp = g((sf).yp, k);                         \
    float fzm = g((sf).zm, k), fzp = g((sf).zp, k);

// W1 prolongation fetch (zero outside domain)
__device__ __forceinline__ float wmat(const float* __restrict__ w1, int z, int y, int x) {
    if ((unsigned)z >= (unsigned)DD || (unsigned)y >= (unsigned)HH || (unsigned)x >= (unsigned)WW)
        return 0.0f;
    return w1[((z>>1)*(HH/2) + (y>>1))*(WW/2) + (x>>1)];
}

// ---------------- stage 0: INV = 1/(1+dt*sigma) ----------------
__global__ __launch_bounds__(256) void k_inv(const float4* __restrict__ sg) {
    int i = blockIdx.x*blockDim.x + threadIdx.x;
    if (i >= NQ) return;
    float4 s = sg[i];
    float4 inv;
    inv.x = 1.0f/(1.0f + DT*s.x);
    inv.y = 1.0f/(1.0f + DT*s.y);
    inv.z = 1.0f/(1.0f + DT*s.z);
    inv.w = 1.0f/(1.0f + DT*s.w);
    g_INV4[i] = inv;
}

// ---------------- predictor: BU/BV/BW ----------------
__global__ __launch_bounds__(192) void k_pred(const float* __restrict__ vu,
                                              const float* __restrict__ vv,
                                              const float* __restrict__ vw,
                                              const float* __restrict__ vp) {
    const float* INV = (const float*)g_INV4;
    int x4 = threadIdx.x, y = blockIdx.x*4 + threadIdx.y, z = blockIdx.y;

    St si = gather(INV, z, y, x4);
    St su = gather(vu, z, y, x4); damp(su, si);
    St sv = gather(vv, z, y, x4); damp(sv, si);
    St sw = gather(vw, z, y, x4); damp(sw, si);
    St sp = gather(vp, z, y, x4);

    float4 bu4, bv4, bw4;
#pragma unroll
    for (int k = 0; k < 4; k++) {
        int x = 4*x4 + k;
        int nout = (x==0)+(x==WW-1)+(y==0)+(y==HH-1)+(z==0)+(z==DD-1);
        float hn = 0.5f * (float)nout;
        float invc = g(si.c, k);

        NBRS(su, k, uc, uxm, uxp, uym, uyp, uzm, uzp);
        NBRS(sv, k, vc, vxm, vxp, vym, vyp, vzm, vzp);
        NBRS(sw, k, wc, wxm, wxp, wym, wyp, wzm, wzp);
        NBRS(sp, k, pc, pxm, pxp, pym, pyp, pzm, pzp);
        (void)pc;

        float dxp = 0.5f*(pxp-pxm), dyp = 0.5f*(pyp-pym), dzp = 0.5f*(pzp-pzm);

        float ku = (uxm+uxp+uym+uyp+uzm+uzp - 6.0f*uc) + hn*uc;
        float kv = (vxm+vxp+vym+vyp+vzm+vzp - 6.0f*vc) + hn*vc;
        float kw = (wxm+wxp+wym+wyp+wzm+wzp - 6.0f*wc) + hn*wc;

        float dxu = 0.5f*(uxp-uxm), dyu = 0.5f*(uyp-uym), dzu = 0.5f*(uzp-uzm);
        float dxv = 0.5f*(vxp-vxm), dyv = 0.5f*(vyp-vym), dzv = 0.5f*(vzp-vzm);
        float dxw = 0.5f*(wxp-wxm), dyw = 0.5f*(wyp-wym), dzw = 0.5f*(wzp-wzm);

        setk(bu4, k, (uc + 0.5f*(RE*ku*DT - uc*dxu*DT - vc*dyu*DT - wc*dzu*DT) - dxp*DT) * invc);
        setk(bv4, k, (vc + 0.5f*(RE*kv*DT - uc*dxv*DT - vc*dyv*DT - wc*dzv*DT) - dyp*DT) * invc);
        setk(bw4, k, (wc + 0.5f*(RE*kw*DT - uc*dxw*DT - vc*dyw*DT - wc*dzw*DT) - dzp*DT) * invc);
    }
    int i4 = (z*HH + y)*W4N + x4;
    g_BU4[i4] = bu4; g_BV4[i4] = bv4; g_BW4[i4] = bw4;
}

// ---------------- corrector: write U,V,W ----------------
__global__ __launch_bounds__(192) void k_stage3(const float* __restrict__ vu,
                                                const float* __restrict__ vv,
                                                const float* __restrict__ vw,
                                                const float* __restrict__ vp) {
    const float* BU = (const float*)g_BU4;
    const float* BV = (const float*)g_BV4;
    const float* BW = (const float*)g_BW4;
    int x4 = threadIdx.x, y = blockIdx.x*4 + threadIdx.y, z = blockIdx.y;
    int i4 = (z*HH + y)*W4N + x4;

    St sbu = gather(BU, z, y, x4);
    St sbv = gather(BV, z, y, x4);
    St sbw = gather(BW, z, y, x4);
    St sp  = gather(vp, z, y, x4);

    float4 inv4 = g_INV4[i4];
    float4 u0 = ((const float4*)vu)[i4];
    float4 v0 = ((const float4*)vv)[i4];
    float4 w0 = ((const float4*)vw)[i4];

    float4 un4, vn4, wn4;
#pragma unroll
    for (int k = 0; k < 4; k++) {
        int x = 4*x4 + k;
        int nout = (x==0)+(x==WW-1)+(y==0)+(y==HH-1)+(z==0)+(z==DD-1);
        float hn = 0.5f * (float)nout;
        float invc = g(inv4, k);
        float uc = g(u0,k)*invc, vc = g(v0,k)*invc, wc = g(w0,k)*invc;

        NBRS(sbu, k, buc, buxm, buxp, buym, buyp, buzm, buzp);
        NBRS(sbv, k, bvc, bvxm, bvxp, bvym, bvyp, bvzm, bvzp);
        NBRS(sbw, k, bwc, bwxm, bwxp, bwym, bwyp, bwzm, bwzp);
        NBRS(sp,  k, pc,  pxm,  pxp,  pym,  pyp,  pzm,  pzp);
        (void)pc;

        float dxp = 0.5f*(pxp-pxm), dyp = 0.5f*(pyp-pym), dzp = 0.5f*(pzp-pzm);

        float kub = (buxm+buxp+buym+buyp+buzm+buzp - 6.0f*buc) + hn*buc;
        float kvb = (bvxm+bvxp+bvym+bvyp+bvzm+bvzp - 6.0f*bvc) + hn*bvc;
        float kwb = (bwxm+bwxp+bwym+bwyp+bwzm+bwzp - 6.0f*bwc) + hn*bwc;

        float dx_bu=0.5f*(buxp-buxm), dy_bu=0.5f*(buyp-buym), dz_bu=0.5f*(buzp-buzm);
        float dx_bv=0.5f*(bvxp-bvxm), dy_bv=0.5f*(bvyp-bvym), dz_bv=0.5f*(bvzp-bvzm);
        float dx_bw=0.5f*(bwxp-bwxm), dy_bw=0.5f*(bwyp-bwym), dz_bw=0.5f*(bwzp-bwzm);

        setk(un4, k, (uc + RE*kub*DT - buc*dx_bu*DT - bvc*dy_bu*DT - bwc*dz_bu*DT - dxp*DT) * invc);
        setk(vn4, k, (vc + RE*kvb*DT - buc*dx_bv*DT - bvc*dy_bv*DT - bwc*dz_bv*DT - dyp*DT) * invc);
        setk(wn4, k, (wc + RE*kwb*DT - buc*dx_bw*DT - bvc*dy_bw*DT - bwc*dz_bw*DT - dzp*DT) * invc);
    }
    g_U4[i4] = un4; g_V4[i4] = vn4; g_W4[i4] = wn4;
}

// ------- fine residual (iter 1), x4 form, no B store: r0 = lap(p) - b -------
__global__ __launch_bounds__(192) void k_residb(const float* __restrict__ vp) {
    const float* U = (const float*)g_U4;
    const float* V = (const float*)g_V4;
    const float* W = (const float*)g_W4;
    int x4 = threadIdx.x, y = blockIdx.x*4 + threadIdx.y, z = blockIdx.y;
    int i4 = (z*HH + y)*W4N + x4;

    float4 ucv = ((const float4*)U)[i4];
    int base = (z*HH + y)*WW + 4*x4;
    float uxm_s = (x4 > 0)     ? U[base - 1] : 0.0f;
    float uxp_s = (x4 < W4N-1) ? U[base + 4] : 0.0f;

    const float4* V4 = (const float4*)V;
    float4 vym = (y > 0)    ? V4[(z*HH + y-1)*W4N + x4] : make_float4(0,0,0,0);
    float4 vyp = (y < HH-1) ? V4[(z*HH + y+1)*W4N + x4] : make_float4(0,0,0,0);

    const float4* Wp4 = (const float4*)W;
    float4 wzm = (z > 0)    ? Wp4[((z-1)*HH + y)*W4N + x4] : make_float4(0,0,0,0);
    float4 wzp = (z < DD-1) ? Wp4[((z+1)*HH + y)*W4N + x4] : make_float4(0,0,0,0);

    St sp = gather(vp, z, y, x4);

    float4 r4;
#pragma unroll
    for (int k = 0; k < 4; k++) {
        float uxm = k ? g(ucv,k-1) : uxm_s;
        float uxp = (k<3) ? g(ucv,k+1) : uxp_s;
        float dxu = 0.5f*(uxp - uxm);
        float dyv = 0.5f*(g(vyp,k) - g(vym,k));
        float dzw = 0.5f*(g(wzp,k) - g(wzm,k));
        float b = -(dxu + dyv + dzw) * (1.0f/DT);

        NBRS(sp, k, pc, pxm, pxp, pym, pyp, pzm, pzp);
        float lap = pxm+pxp+pym+pyp+pzm+pzp - 6.0f*pc;
        setk(r4, k, lap - b);
    }
    g_R04[i4] = r4;
}

// ---------------- restriction R0 -> R1 (2x2x2 avg) ----------------
__global__ void k_restrict(const float* __restrict__ src, float* __restrict__ dst,
                           int dz, int dy, int dx) {
    int i = blockIdx.x*blockDim.x + threadIdx.x;
    int n = dz*dy*dx;
    if (i >= n) return;
    int x = i % dx, t = i / dx, y = t % dy, z = t / dy;
    int sy = dy*2, sx = dx*2;
    const float* s = src + ((2*z)*sy + 2*y)*sx + 2*x;
    float sum = s[0] + s[1] + s[sx] + s[sx+1];
    const float* s2 = s + sy*sx;
    sum += s2[0] + s2[1] + s2[sx] + s2[sx+1];
    dst[i] = 0.125f * sum;
}

// -------- fused restriction R1 -> R2 -> R3 (block = one R3 cell) --------
__global__ __launch_bounds__(64) void k_restrict23(float* __restrict__ out_r_opt) {
    int cell = blockIdx.x;                 // 0..6911
    int x3 = cell % 24, t = cell / 24, y3 = t % 24, z3 = t / 24;
    int tid = threadIdx.x;                 // 0..63: one R1 point of the 4x4x4 region
    int x1 = tid & 3, y1 = (tid >> 2) & 3, z1 = tid >> 4;

    float v1 = g_R1[((z3*4+z1)*96 + (y3*4+y1))*96 + (x3*4+x1)];

    __shared__ float sm1[64];
    __shared__ float sm2[8];
    sm1[tid] = v1;
    __syncthreads();
    if (tid < 8) {
        int x2 = tid & 1, y2 = (tid >> 1) & 1, z2 = tid >> 2;
        float r2 = 0.0f;
#pragma unroll
        for (int dz = 0; dz < 2; dz++)
#pragma unroll
            for (int dy = 0; dy < 2; dy++)
#pragma unroll
                for (int dx = 0; dx < 2; dx++)
                    r2 += sm1[((2*z2+dz)<<4) | ((2*y2+dy)<<2) | (2*x2+dx)];
        r2 *= 0.125f;
        g_R2[((z3*2+z2)*48 + (y3*2+y2))*48 + (x3*2+x2)] = r2;
        sm2[tid] = r2;
    }
    __syncthreads();
    if (tid == 0) {
        float r3 = 0.0f;
#pragma unroll
        for (int j = 0; j < 8; j++) r3 += sm2[j];
        r3 *= 0.125f;
        g_R3[(z3*24 + y3)*24 + x3] = r3;
        if (out_r_opt) out_r_opt[(z3*24 + y3)*24 + x3] = r3;
    }
}

// ---- prolong(coarse)*cscale then Jacobi smooth: out = w - A0(w)/diag + r/diag ----
__global__ void k_smooth(const float* __restrict__ coarse, const float* __restrict__ r,
                         float* __restrict__ out, int dz, int dy, int dx, float cscale) {
    int i = blockIdx.x*blockDim.x + threadIdx.x;
    int n = dz*dy*dx;
    if (i >= n) return;
    int x = i % dx, t = i / dx, y = t % dy, z = t / dy;
    int cy = dy >> 1, cx = dx >> 1;
    auto wp = [&](int zz, int yy, int xx) -> float {
        if ((unsigned)zz >= (unsigned)dz || (unsigned)yy >= (unsigned)dy || (unsigned)xx >= (unsigned)dx)
            return 0.0f;
        return cscale * coarse[((zz>>1)*cy + (yy>>1))*cx + (xx>>1)];
    };
    float c = wp(z,y,x);
    float a = wp(z,y,x-1)+wp(z,y,x+1)+wp(z,y-1,x)+wp(z,y+1,x)+wp(z-1,y,x)+wp(z+1,y,x) - 6.0f*c;
    out[i] = c - a*INVD + r[i]*INVD;
}

// -------- fused iter-1 p-update + iter-2 residual (d-trick, x4) --------
// d = -prol(w1) - r0/diag ; P = p + d ; R0b = lap(d) + r0
__global__ __launch_bounds__(192) void k_pup_resid(const float* __restrict__ vp) {
    const float* R0 = (const float*)g_R04;
    int x4 = threadIdx.x, y = blockIdx.x*4 + threadIdx.y, z = blockIdx.y;
    int i4 = (z*HH + y)*W4N + x4;

    St sr = gather(R0, z, y, x4);
    float4 pc4 = ((const float4*)vp)[i4];

    float4 p4, rr4;
#pragma unroll
    for (int k = 0; k < 4; k++) {
        int x = 4*x4 + k;
        NBRS(sr, k, rc, rxm, rxp, rym, ryp, rzm, rzp);

        float dc  = -wmat(g_W1, z, y, x)   - rc  * INVD;
        float dxm = -wmat(g_W1, z, y, x-1) - rxm * INVD;
        float dxp = -wmat(g_W1, z, y, x+1) - rxp * INVD;
        float dym = -wmat(g_W1, z, y-1, x) - rym * INVD;
        float dyp = -wmat(g_W1, z, y+1, x) - ryp * INVD;
        float dzm = -wmat(g_W1, z-1, y, x) - rzm * INVD;
        float dzp = -wmat(g_W1, z+1, y, x) - rzp * INVD;

        float lapd = dxm + dxp + dym + dyp + dzm + dzp - 6.0f*dc;
        setk(p4, k, g(pc4, k) + dc);
        setk(rr4, k, lapd + rc);
    }
    g_P4[i4] = p4;
    g_R0b4[i4] = rr4;
}

// -------- fused iter-2 p-update + final projection + sb --------
__global__ __launch_bounds__(192) void k_pfinal(float* __restrict__ out_p, float* __restrict__ out_wmg,
                                                float* __restrict__ ou, float* __restrict__ ov,
                                                float* __restrict__ ow) {
    const float* P  = (const float*)g_P4;
    const float* R0 = (const float*)g_R0b4;
    int x4 = threadIdx.x, y = blockIdx.x*4 + threadIdx.y, z = blockIdx.y;
    int i4 = (z*HH + y)*W4N + x4;

    St sp = gather(P, z, y, x4);
    St sr = gather(R0, z, y, x4);
    float4 u4 = g_U4[i4], v4 = g_V4[i4], w4 = g_W4[i4], inv4 = g_INV4[i4];

    float4 op4, owm4, ou4, ov4, ow4;
#pragma unroll
    for (int k = 0; k < 4; k++) {
        int x = 4*x4 + k;
        NBRS(sp, k, pc, pxm, pxp, pym, pyp, pzm, pzp);
        NBRS(sr, k, rc, rxm, rxp, rym, ryp, rzm, rzp);

        float wm   = wmat(g_W1, z, y, x);
        float p2c  = pc  - wm                    - rc  * INVD;
        float p2xm = pxm - wmat(g_W1, z, y, x-1) - rxm * INVD;
        float p2xp = pxp - wmat(g_W1, z, y, x+1) - rxp * INVD;
        float p2ym = pym - wmat(g_W1, z, y-1, x) - rym * INVD;
        float p2yp = pyp - wmat(g_W1, z, y+1, x) - ryp * INVD;
        float p2zm = pzm - wmat(g_W1, z-1, y, x) - rzm * INVD;
        float p2zp = pzp - wmat(g_W1, z+1, y, x) - rzp * INVD;

        float dxp = 0.5f*(p2xp - p2xm);
        float dyp = 0.5f*(p2yp - p2ym);
        float dzp = 0.5f*(p2zp - p2zm);

        float invc = g(inv4, k);
        setk(op4, k, p2c);
        setk(owm4, k, wm);
        setk(ou4, k, (g(u4,k) - dxp*DT) * invc);
        setk(ov4, k, (g(v4,k) - dyp*DT) * invc);
        setk(ow4, k, (g(w4,k) - dzp*DT) * invc);
    }
    ((float4*)out_p)[i4]   = op4;
    ((float4*)out_wmg)[i4] = owm4;
    ((float4*)ou)[i4] = ou4;
    ((float4*)ov)[i4] = ov4;
    ((float4*)ow)[i4] = ow4;
}

// ---------------- launch ----------------
extern "C" void kernel_launch(void* const* d_in, const int* in_sizes, int n_in,
                              void* d_out, int out_size) {
    const float* vu = (const float*)d_in[0];
    const float* vv = (const float*)d_in[1];
    const float* vw = (const float*)d_in[2];
    const float* vp = (const float*)d_in[3];
    const float* sg = (const float*)d_in[4];

    float* out     = (float*)d_out;
    float* out_u   = out;
    float* out_v   = out + (size_t)NFULL;
    float* out_w   = out + (size_t)2*NFULL;
    float* out_p   = out + (size_t)3*NFULL;
    float* out_wmg = out + (size_t)4*NFULL;
    float* out_r   = out + (size_t)5*NFULL;

    void *pR0, *pR0b, *pR1, *pR2, *pR3, *pW2, *pW1;
    cudaGetSymbolAddress(&pR0,  g_R04);
    cudaGetSymbolAddress(&pR0b, g_R0b4);
    cudaGetSymbolAddress(&pR1,  g_R1);
    cudaGetSymbolAddress(&pR2,  g_R2);
    cudaGetSymbolAddress(&pR3,  g_R3);
    cudaGetSymbolAddress(&pW2,  g_W2);
    cudaGetSymbolAddress(&pW1,  g_W1);

    dim3 blk(W4N, 4, 1);          // 192 threads
    dim3 grd(HH/4, DD);           // 4608 blocks

    k_inv   <<<(NQ+255)/256, 256>>>((const float4*)sg);
    k_pred  <<<grd, blk>>>(vu, vv, vw, vp);
    k_stage3<<<grd, blk>>>(vu, vv, vw, vp);

    // ---- MG iteration 1 (p = vp) ----
    k_residb<<<grd, blk>>>(vp);
    k_restrict<<<(NL1+255)/256, 256>>>((const float*)pR0, (float*)pR1, 48, 96, 96);
    k_restrict23<<<NL3, 64>>>(nullptr);
    k_smooth<<<(NL2+255)/256, 256>>>((const float*)pR3, (const float*)pR2, (float*)pW2,
                                     24, 48, 48, INVD);
    k_smooth<<<(NL1+255)/256, 256>>>((const float*)pW2, (const float*)pR1, (float*)pW1,
                                     48, 96, 96, 1.0f);

    // ---- fused: P = p1; R0b = lap(d) + r0 ----
    k_pup_resid<<<grd, blk>>>(vp);

    // ---- MG iteration 2 coarse solve ----
    k_restrict<<<(NL1+255)/256, 256>>>((const float*)pR0b, (float*)pR1, 48, 96, 96);
    k_restrict23<<<NL3, 64>>>(out_r);          // also writes final r output
    k_smooth<<<(NL2+255)/256, 256>>>((const float*)pR3, (const float*)pR2, (float*)pW2,
                                     24, 48, 48, INVD);
    k_smooth<<<(NL1+255)/256, 256>>>((const float*)pW2, (const float*)pR1, (float*)pW1,
                                     48, 96, 96, 1.0f);

    k_pfinal<<<grd, blk>>>(out_p, out_wmg, out_u, out_v, out_w);
}

// round 10
// speedup vs baseline: 1.3466x; 1.3466x over previous
#include <cuda_runtime.h>

#define DD 96
#define HH 192
#define WW 192
#define W4N (WW/4)                // 48
#define NFULL (DD*HH*WW)          // 3538944
#define NQ    (NFULL/4)
#define NL1 (48*96*96)            // 442368
#define NL2 (24*48*48)            // 55296
#define NL3 (12*24*24)            // 6912

#define DT   0.01f
#define RE   0.001f
#define INVD (-1.0f/6.0f)         // 1/diag, diag = -6

// ---------------- scratch (device globals, float4-aligned) ----------------
__device__ float4 g_U4[NQ], g_V4[NQ], g_W4[NQ], g_INV4[NQ];
__device__ float4 g_BU4[NQ], g_BV4[NQ], g_BW4[NQ];
__device__ float4 g_R04[NQ], g_R0b4[NQ], g_P4[NQ];
__device__ float g_R1[NL1], g_R2[NL2], g_R3[NL3];
__device__ float g_W2[NL2], g_W1[NL1];

// ---------------- helpers ----------------
__device__ __forceinline__ float g(const float4 v, int k) {
    switch (k) { case 0: return v.x; case 1: return v.y; case 2: return v.z; default: return v.w; }
}
__device__ __forceinline__ void setk(float4& v, int k, float val) {
    switch (k) { case 0: v.x = val; break; case 1: v.y = val; break;
                 case 2: v.z = val; break; default: v.w = val; }
}

struct St { float4 c, ym, yp, zm, zp; float xm, xp; };

__device__ __forceinline__ St gather(const float* __restrict__ f, int z, int y, int x4) {
    St s;
    const float4* f4 = (const float4*)f;
    s.c  = f4[(z*HH + y)*W4N + x4];
    s.ym = (y > 0)    ? f4[(z*HH + y-1)*W4N + x4]   : make_float4(0,0,0,0);
    s.yp = (y < HH-1) ? f4[(z*HH + y+1)*W4N + x4]   : make_float4(0,0,0,0);
    s.zm = (z > 0)    ? f4[((z-1)*HH + y)*W4N + x4] : make_float4(0,0,0,0);
    s.zp = (z < DD-1) ? f4[((z+1)*HH + y)*W4N + x4] : make_float4(0,0,0,0);
    int base = (z*HH + y)*WW + 4*x4;
    s.xm = (x4 > 0)     ? f[base - 1] : 0.0f;
    s.xp = (x4 < W4N-1) ? f[base + 4] : 0.0f;
    return s;
}

__device__ __forceinline__ void damp(St& a, const St& s) {
    a.c.x*=s.c.x;   a.c.y*=s.c.y;   a.c.z*=s.c.z;   a.c.w*=s.c.w;
    a.ym.x*=s.ym.x; a.ym.y*=s.ym.y; a.ym.z*=s.ym.z; a.ym.w*=s.ym.w;
    a.yp.x*=s.yp.x; a.yp.y*=s.yp.y; a.yp.z*=s.yp.z; a.yp.w*=s.yp.w;
    a.zm.x*=s.zm.x; a.zm.y*=s.zm.y; a.zm.z*=s.zm.z; a.zm.w*=s.zm.w;
    a.zp.x*=s.zp.x; a.zp.y*=s.zp.y; a.zp.z*=s.zp.z; a.zp.w*=s.zp.w;
    a.xm*=s.xm;     a.xp*=s.xp;
}

#define NBRS(sf, k, fc, fxm, fxp, fym, fyp, fzm, fzp)                       \
    float fc  = g((sf).c, k);                                               \
    float fxm = (k)     ? g((sf).c, (k)-1) : (sf).xm;                       \
    float fxp = ((k)<3) ? g((sf).c, (k)+1) : (sf).xp;                       \
    float fym = g((sf).ym, k), fyp = g((sf).yp, k);                         \
    float fzm = g((sf).zm, k), fzp = g((sf).zp, k);

// W1 prolongation fetch (zero outside domain)
__device__ __forceinline__ float wmat(const float* __restrict__ w1, int z, int y, int x) {
    if ((unsigned)z >= (unsigned)DD || (unsigned)y >= (unsigned)HH || (unsigned)x >= (unsigned)WW)
        return 0.0f;
    return w1[((z>>1)*(HH/2) + (y>>1))*(WW/2) + (x>>1)];
}

// ---------------- stage 0: INV = 1/(1+dt*sigma) ----------------
__global__ __launch_bounds__(256) void k_inv(const float4* __restrict__ sg) {
    int i = blockIdx.x*blockDim.x + threadIdx.x;
    if (i >= NQ) return;
    float4 s = sg[i];
    float4 inv;
    inv.x = 1.0f/(1.0f + DT*s.x);
    inv.y = 1.0f/(1.0f + DT*s.y);
    inv.z = 1.0f/(1.0f + DT*s.z);
    inv.w = 1.0f/(1.0f + DT*s.w);
    g_INV4[i] = inv;
}

// ---------------- predictor: BU/BV/BW ----------------
__global__ __launch_bounds__(192) void k_pred(const float* __restrict__ vu,
                                              const float* __restrict__ vv,
                                              const float* __restrict__ vw,
                                              const float* __restrict__ vp) {
    const float* INV = (const float*)g_INV4;
    int x4 = threadIdx.x, y = blockIdx.x*4 + threadIdx.y, z = blockIdx.y;

    St si = gather(INV, z, y, x4);
    St su = gather(vu, z, y, x4); damp(su, si);
    St sv = gather(vv, z, y, x4); damp(sv, si);
    St sw = gather(vw, z, y, x4); damp(sw, si);
    St sp = gather(vp, z, y, x4);

    float4 bu4, bv4, bw4;
#pragma unroll
    for (int k = 0; k < 4; k++) {
        int x = 4*x4 + k;
        int nout = (x==0)+(x==WW-1)+(y==0)+(y==HH-1)+(z==0)+(z==DD-1);
        float hn = 0.5f * (float)nout;
        float invc = g(si.c, k);

        NBRS(su, k, uc, uxm, uxp, uym, uyp, uzm, uzp);
        NBRS(sv, k, vc, vxm, vxp, vym, vyp, vzm, vzp);
        NBRS(sw, k, wc, wxm, wxp, wym, wyp, wzm, wzp);
        NBRS(sp, k, pc, pxm, pxp, pym, pyp, pzm, pzp);
        (void)pc;

        float dxp = 0.5f*(pxp-pxm), dyp = 0.5f*(pyp-pym), dzp = 0.5f*(pzp-pzm);

        float ku = (uxm+uxp+uym+uyp+uzm+uzp - 6.0f*uc) + hn*uc;
        float kv = (vxm+vxp+vym+vyp+vzm+vzp - 6.0f*vc) + hn*vc;
        float kw = (wxm+wxp+wym+wyp+wzm+wzp - 6.0f*wc) + hn*wc;

        float dxu = 0.5f*(uxp-uxm), dyu = 0.5f*(uyp-uym), dzu = 0.5f*(uzp-uzm);
        float dxv = 0.5f*(vxp-vxm), dyv = 0.5f*(vyp-vym), dzv = 0.5f*(vzp-vzm);
        float dxw = 0.5f*(wxp-wxm), dyw = 0.5f*(wyp-wym), dzw = 0.5f*(wzp-wzm);

        setk(bu4, k, (uc + 0.5f*(RE*ku*DT - uc*dxu*DT - vc*dyu*DT - wc*dzu*DT) - dxp*DT) * invc);
        setk(bv4, k, (vc + 0.5f*(RE*kv*DT - uc*dxv*DT - vc*dyv*DT - wc*dzv*DT) - dyp*DT) * invc);
        setk(bw4, k, (wc + 0.5f*(RE*kw*DT - uc*dxw*DT - vc*dyw*DT - wc*dzw*DT) - dzp*DT) * invc);
    }
    int i4 = (z*HH + y)*W4N + x4;
    g_BU4[i4] = bu4; g_BV4[i4] = bv4; g_BW4[i4] = bw4;
}

// ---------------- corrector: write U,V,W ----------------
__global__ __launch_bounds__(192) void k_stage3(const float* __restrict__ vu,
                                                const float* __restrict__ vv,
                                                const float* __restrict__ vw,
                                                const float* __restrict__ vp) {
    const float* BU = (const float*)g_BU4;
    const float* BV = (const float*)g_BV4;
    const float* BW = (const float*)g_BW4;
    int x4 = threadIdx.x, y = blockIdx.x*4 + threadIdx.y, z = blockIdx.y;
    int i4 = (z*HH + y)*W4N + x4;

    St sbu = gather(BU, z, y, x4);
    St sbv = gather(BV, z, y, x4);
    St sbw = gather(BW, z, y, x4);
    St sp  = gather(vp, z, y, x4);

    float4 inv4 = g_INV4[i4];
    float4 u0 = ((const float4*)vu)[i4];
    float4 v0 = ((const float4*)vv)[i4];
    float4 w0 = ((const float4*)vw)[i4];

    float4 un4, vn4, wn4;
#pragma unroll
    for (int k = 0; k < 4; k++) {
        int x = 4*x4 + k;
        int nout = (x==0)+(x==WW-1)+(y==0)+(y==HH-1)+(z==0)+(z==DD-1);
        float hn = 0.5f * (float)nout;
        float invc = g(inv4, k);
        float uc = g(u0,k)*invc, vc = g(v0,k)*invc, wc = g(w0,k)*invc;

        NBRS(sbu, k, buc, buxm, buxp, buym, buyp, buzm, buzp);
        NBRS(sbv, k, bvc, bvxm, bvxp, bvym, bvyp, bvzm, bvzp);
        NBRS(sbw, k, bwc, bwxm, bwxp, bwym, bwyp, bwzm, bwzp);
        NBRS(sp,  k, pc,  pxm,  pxp,  pym,  pyp,  pzm,  pzp);
        (void)pc;

        float dxp = 0.5f*(pxp-pxm), dyp = 0.5f*(pyp-pym), dzp = 0.5f*(pzp-pzm);

        float kub = (buxm+buxp+buym+buyp+buzm+buzp - 6.0f*buc) + hn*buc;
        float kvb = (bvxm+bvxp+bvym+bvyp+bvzm+bvzp - 6.0f*bvc) + hn*bvc;
        float kwb = (bwxm+bwxp+bwym+bwyp+bwzm+bwzp - 6.0f*bwc) + hn*bwc;

        float dx_bu=0.5f*(buxp-buxm), dy_bu=0.5f*(buyp-buym), dz_bu=0.5f*(buzp-buzm);
        float dx_bv=0.5f*(bvxp-bvxm), dy_bv=0.5f*(bvyp-bvym), dz_bv=0.5f*(bvzp-bvzm);
        float dx_bw=0.5f*(bwxp-bwxm), dy_bw=0.5f*(bwyp-bwym), dz_bw=0.5f*(bwzp-bwzm);

        setk(un4, k, (uc + RE*kub*DT - buc*dx_bu*DT - bvc*dy_bu*DT - bwc*dz_bu*DT - dxp*DT) * invc);
        setk(vn4, k, (vc + RE*kvb*DT - buc*dx_bv*DT - bvc*dy_bv*DT - bwc*dz_bv*DT - dyp*DT) * invc);
        setk(wn4, k, (wc + RE*kwb*DT - buc*dx_bw*DT - bvc*dy_bw*DT - bwc*dz_bw*DT - dzp*DT) * invc);
    }
    g_U4[i4] = un4; g_V4[i4] = vn4; g_W4[i4] = wn4;
}

// ------- fine residual (iter 1), x4 form, no B store: r0 = lap(p) - b -------
__global__ __launch_bounds__(192) void k_residb(const float* __restrict__ vp) {
    const float* U = (const float*)g_U4;
    const float* V = (const float*)g_V4;
    const float* W = (const float*)g_W4;
    int x4 = threadIdx.x, y = blockIdx.x*4 + threadIdx.y, z = blockIdx.y;
    int i4 = (z*HH + y)*W4N + x4;

    float4 ucv = ((const float4*)U)[i4];
    int base = (z*HH + y)*WW + 4*x4;
    float uxm_s = (x4 > 0)     ? U[base - 1] : 0.0f;
    float uxp_s = (x4 < W4N-1) ? U[base + 4] : 0.0f;

    const float4* V4 = (const float4*)V;
    float4 vym = (y > 0)    ? V4[(z*HH + y-1)*W4N + x4] : make_float4(0,0,0,0);
    float4 vyp = (y < HH-1) ? V4[(z*HH + y+1)*W4N + x4] : make_float4(0,0,0,0);

    const float4* Wp4 = (const float4*)W;
    float4 wzm = (z > 0)    ? Wp4[((z-1)*HH + y)*W4N + x4] : make_float4(0,0,0,0);
    float4 wzp = (z < DD-1) ? Wp4[((z+1)*HH + y)*W4N + x4] : make_float4(0,0,0,0);

    St sp = gather(vp, z, y, x4);

    float4 r4;
#pragma unroll
    for (int k = 0; k < 4; k++) {
        float uxm = k ? g(ucv,k-1) : uxm_s;
        float uxp = (k<3) ? g(ucv,k+1) : uxp_s;
        float dxu = 0.5f*(uxp - uxm);
        float dyv = 0.5f*(g(vyp,k) - g(vym,k));
        float dzw = 0.5f*(g(wzp,k) - g(wzm,k));
        float b = -(dxu + dyv + dzw) * (1.0f/DT);

        NBRS(sp, k, pc, pxm, pxp, pym, pyp, pzm, pzp);
        float lap = pxm+pxp+pym+pyp+pzm+pzp - 6.0f*pc;
        setk(r4, k, lap - b);
    }
    g_R04[i4] = r4;
}

// ---------------- generic restriction (2x2x2 avg, stride 2) ----------------
// optional mirror output (used on the last level of iter 2 to produce out_r)
__global__ void k_restrict(const float* __restrict__ src, float* __restrict__ dst,
                           int dz, int dy, int dx, float* __restrict__ mirror) {
    int i = blockIdx.x*blockDim.x + threadIdx.x;
    int n = dz*dy*dx;
    if (i >= n) return;
    int x = i % dx, t = i / dx, y = t % dy, z = t / dy;
    int sy = dy*2, sx = dx*2;
    const float* s = src + ((2*z)*sy + 2*y)*sx + 2*x;
    float sum = s[0] + s[1] + s[sx] + s[sx+1];
    const float* s2 = s + sy*sx;
    sum += s2[0] + s2[1] + s2[sx] + s2[sx+1];
    float r = 0.125f * sum;
    dst[i] = r;
    if (mirror) mirror[i] = r;
}

// ---- prolong(coarse)*cscale then Jacobi smooth: out = w - A0(w)/diag + r/diag ----
__global__ void k_smooth(const float* __restrict__ coarse, const float* __restrict__ r,
                         float* __restrict__ out, int dz, int dy, int dx, float cscale) {
    int i = blockIdx.x*blockDim.x + threadIdx.x;
    int n = dz*dy*dx;
    if (i >= n) return;
    int x = i % dx, t = i / dx, y = t % dy, z = t / dy;
    int cy = dy >> 1, cx = dx >> 1;
    auto wp = [&](int zz, int yy, int xx) -> float {
        if ((unsigned)zz >= (unsigned)dz || (unsigned)yy >= (unsigned)dy || (unsigned)xx >= (unsigned)dx)
            return 0.0f;
        return cscale * coarse[((zz>>1)*cy + (yy>>1))*cx + (xx>>1)];
    };
    float c = wp(z,y,x);
    float a = wp(z,y,x-1)+wp(z,y,x+1)+wp(z,y-1,x)+wp(z,y+1,x)+wp(z-1,y,x)+wp(z+1,y,x) - 6.0f*c;
    out[i] = c - a*INVD + r[i]*INVD;
}

// -------- fused iter-1 p-update + iter-2 residual (d-trick, x4) --------
// d = -prol(w1) - r0/diag ; P = p + d ; R0b = lap(d) + r0
__global__ __launch_bounds__(192) void k_pup_resid(const float* __restrict__ vp) {
    const float* R0 = (const float*)g_R04;
    int x4 = threadIdx.x, y = blockIdx.x*4 + threadIdx.y, z = blockIdx.y;
    int i4 = (z*HH + y)*W4N + x4;

    St sr = gather(R0, z, y, x4);
    float4 pc4 = ((const float4*)vp)[i4];

    float4 p4, rr4;
#pragma unroll
    for (int k = 0; k < 4; k++) {
        int x = 4*x4 + k;
        NBRS(sr, k, rc, rxm, rxp, rym, ryp, rzm, rzp);

        float dc  = -wmat(g_W1, z, y, x)   - rc  * INVD;
        float dxm = -wmat(g_W1, z, y, x-1) - rxm * INVD;
        float dxp = -wmat(g_W1, z, y, x+1) - rxp * INVD;
        float dym = -wmat(g_W1, z, y-1, x) - rym * INVD;
        float dyp = -wmat(g_W1, z, y+1, x) - ryp * INVD;
        float dzm = -wmat(g_W1, z-1, y, x) - rzm * INVD;
        float dzp = -wmat(g_W1, z+1, y, x) - rzp * INVD;

        float lapd = dxm + dxp + dym + dyp + dzm + dzp - 6.0f*dc;
        setk(p4, k, g(pc4, k) + dc);
        setk(rr4, k, lapd + rc);
    }
    g_P4[i4] = p4;
    g_R0b4[i4] = rr4;
}

// -------- fused iter-2 p-update + final projection + sb --------
__global__ __launch_bounds__(192) void k_pfinal(float* __restrict__ out_p, float* __restrict__ out_wmg,
                                                float* __restrict__ ou, float* __restrict__ ov,
                                                float* __restrict__ ow) {
    const float* P  = (const float*)g_P4;
    const float* R0 = (const float*)g_R0b4;
    int x4 = threadIdx.x, y = blockIdx.x*4 + threadIdx.y, z = blockIdx.y;
    int i4 = (z*HH + y)*W4N + x4;

    St sp = gather(P, z, y, x4);
    St sr = gather(R0, z, y, x4);
    float4 u4 = g_U4[i4], v4 = g_V4[i4], w4 = g_W4[i4], inv4 = g_INV4[i4];

    float4 op4, owm4, ou4, ov4, ow4;
#pragma unroll
    for (int k = 0; k < 4; k++) {
        int x = 4*x4 + k;
        NBRS(sp, k, pc, pxm, pxp, pym, pyp, pzm, pzp);
        NBRS(sr, k, rc, rxm, rxp, rym, ryp, rzm, rzp);

        float wm   = wmat(g_W1, z, y, x);
        float p2c  = pc  - wm                    - rc  * INVD;
        float p2xm = pxm - wmat(g_W1, z, y, x-1) - rxm * INVD;
        float p2xp = pxp - wmat(g_W1, z, y, x+1) - rxp * INVD;
        float p2ym = pym - wmat(g_W1, z, y-1, x) - rym * INVD;
        float p2yp = pyp - wmat(g_W1, z, y+1, x) - ryp * INVD;
        float p2zm = pzm - wmat(g_W1, z-1, y, x) - rzm * INVD;
        float p2zp = pzp - wmat(g_W1, z+1, y, x) - rzp * INVD;

        float dxp = 0.5f*(p2xp - p2xm);
        float dyp = 0.5f*(p2yp - p2ym);
        float dzp = 0.5f*(p2zp - p2zm);

        float invc = g(inv4, k);
        setk(op4, k, p2c);
        setk(owm4, k, wm);
        setk(ou4, k, (g(u4,k) - dxp*DT) * invc);
        setk(ov4, k, (g(v4,k) - dyp*DT) * invc);
        setk(ow4, k, (g(w4,k) - dzp*DT) * invc);
    }
    ((float4*)out_p)[i4]   = op4;
    ((float4*)out_wmg)[i4] = owm4;
    ((float4*)ou)[i4] = ou4;
    ((float4*)ov)[i4] = ov4;
    ((float4*)ow)[i4] = ow4;
}

// ---------------- launch ----------------
extern "C" void kernel_launch(void* const* d_in, const int* in_sizes, int n_in,
                              void* d_out, int out_size) {
    const float* vu = (const float*)d_in[0];
    const float* vv = (const float*)d_in[1];
    const float* vw = (const float*)d_in[2];
    const float* vp = (const float*)d_in[3];
    const float* sg = (const float*)d_in[4];

    float* out     = (float*)d_out;
    float* out_u   = out;
    float* out_v   = out + (size_t)NFULL;
    float* out_w   = out + (size_t)2*NFULL;
    float* out_p   = out + (size_t)3*NFULL;
    float* out_wmg = out + (size_t)4*NFULL;
    float* out_r   = out + (size_t)5*NFULL;

    void *pR0, *pR0b, *pR1, *pR2, *pR3, *pW2, *pW1;
    cudaGetSymbolAddress(&pR0,  g_R04);
    cudaGetSymbolAddress(&pR0b, g_R0b4);
    cudaGetSymbolAddress(&pR1,  g_R1);
    cudaGetSymbolAddress(&pR2,  g_R2);
    cudaGetSymbolAddress(&pR3,  g_R3);
    cudaGetSymbolAddress(&pW2,  g_W2);
    cudaGetSymbolAddress(&pW1,  g_W1);

    dim3 blk(W4N, 4, 1);          // 192 threads
    dim3 grd(HH/4, DD);           // 4608 blocks

    k_inv   <<<(NQ+255)/256, 256>>>((const float4*)sg);
    k_pred  <<<grd, blk>>>(vu, vv, vw, vp);
    k_stage3<<<grd, blk>>>(vu, vv, vw, vp);

    // ---- MG iteration 1 (p = vp) ----
    k_residb<<<grd, blk>>>(vp);
    k_restrict<<<(NL1+255)/256, 256>>>((const float*)pR0, (float*)pR1, 48, 96, 96, nullptr);
    k_restrict<<<(NL2+255)/256, 256>>>((const float*)pR1, (float*)pR2, 24, 48, 48, nullptr);
    k_restrict<<<(NL3+255)/256, 256>>>((const float*)pR2, (float*)pR3, 12, 24, 24, nullptr);
    k_smooth<<<(NL2+255)/256, 256>>>((const float*)pR3, (const float*)pR2, (float*)pW2,
                                     24, 48, 48, INVD);
    k_smooth<<<(NL1+255)/256, 256>>>((const float*)pW2, (const float*)pR1, (float*)pW1,
                                     48, 96, 96, 1.0f);

    // ---- fused: P = p1; R0b = lap(d) + r0 ----
    k_pup_resid<<<grd, blk>>>(vp);

    // ---- MG iteration 2 coarse solve ----
    k_restrict<<<(NL1+255)/256, 256>>>((const float*)pR0b, (float*)pR1, 48, 96, 96, nullptr);
    k_restrict<<<(NL2+255)/256, 256>>>((const float*)pR1, (float*)pR2, 24, 48, 48, nullptr);
    k_restrict<<<(NL3+255)/256, 256>>>((const float*)pR2, (float*)pR3, 12, 24, 24, out_r);
    k_smooth<<<(NL2+255)/256, 256>>>((const float*)pR3, (const float*)pR2, (float*)pW2,
                                     24, 48, 48, INVD);
    k_smooth<<<(NL1+255)/256, 256>>>((const float*)pW2, (const float*)pR1, (float*)pW1,
                                     48, 96, 96, 1.0f);

    k_pfinal<<<grd, blk>>>(out_p, out_wmg, out_u, out_v, out_w);
}